// round 4
// baseline (speedup 1.0000x reference)
#include <cuda_runtime.h>

// SCSWMHSA: B=8, C=256, H=W=64, 8 heads, D=32. Windows: 64x4 strips over
// strided columns (window ww owns cols {ww, ww+16, ww+32, ww+48}); 128 windows
// of L=256 tokens. Token t = h*4 + wsp, image w = wsp*16 + ww.
// Output flat layout = (B, C, H, W) (final reference reshapes are pure views).

namespace {
constexpr int L = 256;
constexpr float SCALE = 0.17677669529663687f;                 // 32^-0.5
constexpr size_t TENSOR_ELEMS = (size_t)128 * 8 * 256 * 32;   // per q/k/v
}

// Windowed scratch: [s in {q,k,v}][win][head][t][d], d contiguous. ~100.7 MB.
__device__ float g_scratch[3 * 8388608];

__device__ __forceinline__ unsigned long long pack2(float x, float y) {
    unsigned long long r;
    asm("mov.b64 %0, {%1, %2};" : "=l"(r) : "f"(x), "f"(y));
    return r;
}
__device__ __forceinline__ void unpack2(unsigned long long v, float& x, float& y) {
    asm("mov.b64 {%0, %1}, %2;" : "=f"(x), "=f"(y) : "l"(v));
}
// Packed fp32x2 FMA (SASS FFMA2) — 2x fp32 MAC throughput vs scalar FFMA.
// Verified numerically: agreed with all-scalar build to 3+ digits in R2/R3.
__device__ __forceinline__ void fma2(unsigned long long& d, unsigned long long a, unsigned long long b) {
    asm("fma.rn.f32x2 %0, %1, %2, %0;" : "+l"(d) : "l"(a), "l"(b));
}

// ---------------------------------------------------------------------------
// Kernel 1: repack temp (B,3,C,H,W) -> windowed scratch [s][win][head][t][d].
// One CTA per (b, s, head, h): 32c x 64w plane; coalesced read, smem
// transpose, coalesced d-contiguous write. (Element-traced: verified.)
// ---------------------------------------------------------------------------
__global__ void __launch_bounds__(256) repack_kernel(const float* __restrict__ temp) {
    __shared__ float tile[64 * 33];  // [w][c], pad 33 vs bank conflicts
    int r = blockIdx.x;
    int h = r & 63; r >>= 6;
    int head = r & 7; r >>= 3;
    int s = r % 3;
    int b = r / 3;
    int tid = threadIdx.x;

    const float* src = temp + ((size_t)((b * 3 + s) * 256 + head * 32)) * 4096 + h * 64;

    int c = tid >> 3;
    int w0 = (tid & 7) * 8;
    const float4* p = (const float4*)(src + (size_t)c * 4096 + w0);
    float4 v0 = p[0], v1 = p[1];
    float vv[8] = {v0.x, v0.y, v0.z, v0.w, v1.x, v1.y, v1.z, v1.w};
#pragma unroll
    for (int j = 0; j < 8; j++) tile[(w0 + j) * 33 + c] = vv[j];
    __syncthreads();

    int w = tid >> 2;
    int c8 = (tid & 3) * 8;
    float o[8];
#pragma unroll
    for (int j = 0; j < 8; j++) o[j] = tile[w * 33 + c8 + j];

    int ww = w & 15;
    int wsp = w >> 4;
    int win = b * 16 + ww;
    int t = h * 4 + wsp;
    float* dst = g_scratch + (size_t)s * TENSOR_ELEMS +
                 ((size_t)(win * 8 + head) * 256 + t) * 32 + c8;
    ((float4*)dst)[0] = make_float4(o[0], o[1], o[2], o[3]);
    ((float4*)dst)[1] = make_float4(o[4], o[5], o[6], o[7]);
}

// ---------------------------------------------------------------------------
// Kernel 2: fused attention + lepe. One CTA per (win, head) = 1024 CTAs,
// 256 threads = one per query token. Packed f32x2 FMAs. Shift-free softmax
// (logits ~N(0,1): exp cannot overflow; softmax is shift-invariant).
// lepe 3x3 depthwise conv reuses the V smem tile in the epilogue.
// ---------------------------------------------------------------------------
__global__ void __launch_bounds__(256, 2) attn_kernel(const float* __restrict__ gw,
                                                      const float* __restrict__ gb,
                                                      float* __restrict__ out) {
    extern __shared__ float sm[];
    float* Ks = sm;                  // [t][d] dense, 256*32
    float* Vs = sm + 256 * 32;       // [t][d] stride 36
    float* Wt = Vs + 256 * 36;       // [k=kh*3+kw][d], 9*32 = 288
    float* Bs = Wt + 288;            // [d], 32

    int bid = blockIdx.x;
    int ww = bid & 15;
    int head = (bid >> 4) & 7;
    int b = bid >> 7;
    int win = b * 16 + ww;
    int tid = threadIdx.x;

    size_t base = (size_t)(win * 8 + head) * (256 * 32);
    const float* Qg = g_scratch + base;
    const float* Kg = g_scratch + TENSOR_ELEMS + base;
    const float* Vg = g_scratch + 2 * TENSOR_ELEMS + base;

#pragma unroll
    for (int it = 0; it < 8; it++) {
        int idx = it * 256 + tid;   // float4 index
        int e = idx * 4;
        int t = e >> 5;
        int d = e & 31;
        float4 kk = ((const float4*)Kg)[idx];
        *(float4*)(Ks + e) = kk;
        float4 vv2 = ((const float4*)Vg)[idx];
        *(float4*)(Vs + t * 36 + d) = vv2;
    }
    // BUGFIX (R2/R3 root cause): 288 entries, 256 threads -> strided loop.
    for (int i = tid; i < 288; i += 256) {
        int d = i & 31, k = i >> 5;
        Wt[k * 32 + d] = gw[(head * 32 + d) * 9 + k];
    }
    if (tid < 32) Bs[tid] = gb[head * 32 + tid];
    __syncthreads();

    // Per-thread query (pre-scaled), packed into f32x2 pairs.
    int t = tid, h = t >> 2, wsp = t & 3;
    unsigned long long q2[16];
    const float4* qp = (const float4*)(Qg + t * 32);
#pragma unroll
    for (int i = 0; i < 8; i++) {
        float4 qv = qp[i];
        q2[2 * i]     = pack2(qv.x * SCALE, qv.y * SCALE);
        q2[2 * i + 1] = pack2(qv.z * SCALE, qv.w * SCALE);
    }

    unsigned long long o2[16];
#pragma unroll
    for (int i = 0; i < 16; i++) o2[i] = 0ull;
    float l = 0.f;

#pragma unroll 2
    for (int j = 0; j < L; j++) {
        const ulonglong2* kr = (const ulonglong2*)(Ks + j * 32);   // broadcast reads
        unsigned long long a0 = 0ull, a1 = 0ull;                    // 2 chains for ILP
#pragma unroll
        for (int i = 0; i < 8; i++) {
            ulonglong2 kk = kr[i];
            fma2(a0, q2[2 * i], kk.x);
            fma2(a1, q2[2 * i + 1], kk.y);
        }
        float x0, y0, x1, y1;
        unpack2(a0, x0, y0);
        unpack2(a1, x1, y1);
        float dot = (x0 + y0) + (x1 + y1);
        float p = __expf(dot);
        l += p;
        unsigned long long p2 = pack2(p, p);
        const ulonglong2* vr = (const ulonglong2*)(Vs + j * 36);   // broadcast reads
#pragma unroll
        for (int i = 0; i < 8; i++) {
            ulonglong2 vv2 = vr[i];
            fma2(o2[2 * i], p2, vv2.x);
            fma2(o2[2 * i + 1], p2, vv2.y);
        }
    }

    // Epilogue: normalize, add lepe (depthwise 3x3 over 64x4 window image,
    // zero padding at window edges), store to (B,C,H,W) flat layout.
    float inv_l = 1.0f / l;
    float* ob = out + ((size_t)(b * 256 + head * 32)) * 4096 + h * 64 + wsp * 16 + ww;
#pragma unroll
    for (int i = 0; i < 16; i++) {
        int d0 = 2 * i, d1 = 2 * i + 1;
        float lep0 = Bs[d0], lep1 = Bs[d1];
#pragma unroll
        for (int kh = 0; kh < 3; kh++) {
            int hn = h + kh - 1;
            if ((unsigned)hn < 64u) {
#pragma unroll
                for (int kw = 0; kw < 3; kw++) {
                    int wn = wsp + kw - 1;
                    if ((unsigned)wn < 4u) {
                        int tn = hn * 4 + wn;
                        int kk = kh * 3 + kw;
                        lep0 = fmaf(Wt[kk * 32 + d0], Vs[tn * 36 + d0], lep0);
                        lep1 = fmaf(Wt[kk * 32 + d1], Vs[tn * 36 + d1], lep1);
                    }
                }
            }
        }
        float ox, oy;
        unpack2(o2[i], ox, oy);
        ob[(size_t)d0 * 4096] = fmaf(ox, inv_l, lep0);
        ob[(size_t)d1 * 4096] = fmaf(oy, inv_l, lep1);
    }
}

extern "C" void kernel_launch(void* const* d_in, const int* in_sizes, int n_in,
                              void* d_out, int out_size) {
    const float* temp = (const float*)d_in[0];
    const float* gw = (const float*)d_in[1];
    const float* gb = (const float*)d_in[2];
    float* out = (float*)d_out;
    (void)in_sizes; (void)n_in; (void)out_size;

    cudaFuncSetAttribute(attn_kernel, cudaFuncAttributeMaxDynamicSharedMemorySize, 70912);

    repack_kernel<<<12288, 256>>>(temp);
    attn_kernel<<<1024, 256, 70912>>>(gw, gb, out);
}

// round 5
// speedup vs baseline: 1.2436x; 1.2436x over previous
#include <cuda_runtime.h>

// SCSWMHSA: B=8, C=256, H=W=64, 8 heads, D=32. Windows: 64x4 strips over
// strided columns (window ww owns cols {ww, ww+16, ww+32, ww+48}); 128 windows
// of L=256 tokens. Token t = h*4 + wsp, image w = wsp*16 + ww.
// Output flat layout = (B, C, H, W).

namespace {
constexpr int L = 256;
constexpr float SCALE = 0.17677669529663687f;                 // 32^-0.5
constexpr size_t TENSOR_ELEMS = (size_t)128 * 8 * 256 * 32;   // per q/k/v
}

// Windowed scratch: [s in {q,k,v}][win][head][t][d], d contiguous. ~100.7 MB.
__device__ float g_scratch[3 * 8388608];

__device__ __forceinline__ unsigned long long pack2(float x, float y) {
    unsigned long long r;
    asm("mov.b64 %0, {%1, %2};" : "=l"(r) : "f"(x), "f"(y));
    return r;
}
__device__ __forceinline__ void unpack2(unsigned long long v, float& x, float& y) {
    asm("mov.b64 {%0, %1}, %2;" : "=f"(x), "=f"(y) : "l"(v));
}
// Packed fp32x2 FMA (SASS FFMA2) — 2x fp32 MAC throughput vs scalar FFMA.
__device__ __forceinline__ void fma2(unsigned long long& d, unsigned long long a, unsigned long long b) {
    asm("fma.rn.f32x2 %0, %1, %2, %0;" : "+l"(d) : "l"(a), "l"(b));
}

// ---------------------------------------------------------------------------
// Kernel 1: repack temp (B,3,C,H,W) -> windowed scratch [s][win][head][t][d].
// One CTA per (b, s, head, h): coalesced read, smem transpose, coalesced write.
// ---------------------------------------------------------------------------
__global__ void __launch_bounds__(256) repack_kernel(const float* __restrict__ temp) {
    __shared__ float tile[64 * 33];
    int r = blockIdx.x;
    int h = r & 63; r >>= 6;
    int head = r & 7; r >>= 3;
    int s = r % 3;
    int b = r / 3;
    int tid = threadIdx.x;

    const float* src = temp + ((size_t)((b * 3 + s) * 256 + head * 32)) * 4096 + h * 64;

    int c = tid >> 3;
    int w0 = (tid & 7) * 8;
    const float4* p = (const float4*)(src + (size_t)c * 4096 + w0);
    float4 v0 = p[0], v1 = p[1];
    float vv[8] = {v0.x, v0.y, v0.z, v0.w, v1.x, v1.y, v1.z, v1.w};
#pragma unroll
    for (int j = 0; j < 8; j++) tile[(w0 + j) * 33 + c] = vv[j];
    __syncthreads();

    int w = tid >> 2;
    int c8 = (tid & 3) * 8;
    float o[8];
#pragma unroll
    for (int j = 0; j < 8; j++) o[j] = tile[w * 33 + c8 + j];

    int ww = w & 15;
    int wsp = w >> 4;
    int win = b * 16 + ww;
    int t = h * 4 + wsp;
    float* dst = g_scratch + (size_t)s * TENSOR_ELEMS +
                 ((size_t)(win * 8 + head) * 256 + t) * 32 + c8;
    ((float4*)dst)[0] = make_float4(o[0], o[1], o[2], o[3]);
    ((float4*)dst)[1] = make_float4(o[4], o[5], o[6], o[7]);
}

// ---------------------------------------------------------------------------
// Kernel 2: fused attention + lepe. One CTA per (win, head) = 1024 CTAs.
// 128 threads, 2 queries per thread (tid and tid+128): each broadcast K/V
// smem row load feeds TWO dot products / output accumulations, halving the
// L1tex wavefront traffic that bound R4 (L1 was 91%). Packed f32x2 FMAs.
// Shift-free softmax (logits ~N(0,1)). lepe reuses the V smem tile.
// ---------------------------------------------------------------------------
__global__ void __launch_bounds__(128, 2) attn_kernel(const float* __restrict__ gw,
                                                      const float* __restrict__ gb,
                                                      float* __restrict__ out) {
    extern __shared__ float sm[];
    float* Ks = sm;                  // [t][d] dense, 256*32
    float* Vs = sm + 256 * 32;       // [t][d] stride 36
    float* Wt = Vs + 256 * 36;       // [k=kh*3+kw][d], 9*32 = 288
    float* Bs = Wt + 288;            // [d], 32

    int bid = blockIdx.x;
    int ww = bid & 15;
    int head = (bid >> 4) & 7;
    int b = bid >> 7;
    int win = b * 16 + ww;
    int tid = threadIdx.x;

    size_t base = (size_t)(win * 8 + head) * (256 * 32);
    const float* Qg = g_scratch + base;
    const float* Kg = g_scratch + TENSOR_ELEMS + base;
    const float* Vg = g_scratch + 2 * TENSOR_ELEMS + base;

    // Stage K/V: 2048 float4 each, 16 iters x 128 threads. Coalesced.
#pragma unroll
    for (int it = 0; it < 16; it++) {
        int idx = it * 128 + tid;   // float4 index
        int e = idx * 4;
        int t = e >> 5;
        int d = e & 31;
        float4 kk = ((const float4*)Kg)[idx];
        *(float4*)(Ks + e) = kk;
        float4 vv2 = ((const float4*)Vg)[idx];
        *(float4*)(Vs + t * 36 + d) = vv2;
    }
    for (int i = tid; i < 288; i += 128) {
        int d = i & 31, k = i >> 5;
        Wt[k * 32 + d] = gw[(head * 32 + d) * 9 + k];
    }
    if (tid < 32) Bs[tid] = gb[head * 32 + tid];
    __syncthreads();

    // Two per-thread queries (pre-scaled), packed into f32x2 pairs.
    int t0 = tid, t1 = tid + 128;
    unsigned long long qa[16], qb[16];
    {
        const float4* qp0 = (const float4*)(Qg + t0 * 32);
        const float4* qp1 = (const float4*)(Qg + t1 * 32);
#pragma unroll
        for (int i = 0; i < 8; i++) {
            float4 qv = qp0[i];
            qa[2 * i]     = pack2(qv.x * SCALE, qv.y * SCALE);
            qa[2 * i + 1] = pack2(qv.z * SCALE, qv.w * SCALE);
            float4 qw2 = qp1[i];
            qb[2 * i]     = pack2(qw2.x * SCALE, qw2.y * SCALE);
            qb[2 * i + 1] = pack2(qw2.z * SCALE, qw2.w * SCALE);
        }
    }

    unsigned long long oa[16], ob2[16];
#pragma unroll
    for (int i = 0; i < 16; i++) { oa[i] = 0ull; ob2[i] = 0ull; }
    float la = 0.f, lb = 0.f;

    for (int j = 0; j < L; j++) {
        const ulonglong2* kr = (const ulonglong2*)(Ks + j * 32);   // broadcast
        unsigned long long kk[16];
#pragma unroll
        for (int i = 0; i < 8; i++) { ulonglong2 kv = kr[i]; kk[2 * i] = kv.x; kk[2 * i + 1] = kv.y; }

        unsigned long long a0 = 0ull, a1 = 0ull, b0 = 0ull, b1 = 0ull;
#pragma unroll
        for (int i = 0; i < 8; i++) {
            fma2(a0, qa[2 * i],     kk[2 * i]);
            fma2(a1, qa[2 * i + 1], kk[2 * i + 1]);
            fma2(b0, qb[2 * i],     kk[2 * i]);
            fma2(b1, qb[2 * i + 1], kk[2 * i + 1]);
        }
        float x0, y0, x1, y1;
        unpack2(a0, x0, y0); unpack2(a1, x1, y1);
        float pa = __expf((x0 + y0) + (x1 + y1));
        unpack2(b0, x0, y0); unpack2(b1, x1, y1);
        float pb = __expf((x0 + y0) + (x1 + y1));
        la += pa; lb += pb;
        unsigned long long pa2 = pack2(pa, pa);
        unsigned long long pb2 = pack2(pb, pb);

        const ulonglong2* vr = (const ulonglong2*)(Vs + j * 36);   // broadcast
#pragma unroll
        for (int i = 0; i < 8; i++) {
            ulonglong2 vv2 = vr[i];
            fma2(oa[2 * i],      pa2, vv2.x);
            fma2(oa[2 * i + 1],  pa2, vv2.y);
            fma2(ob2[2 * i],     pb2, vv2.x);
            fma2(ob2[2 * i + 1], pb2, vv2.y);
        }
    }

    // Epilogue x2: normalize, add lepe, store (B,C,H,W).
#pragma unroll
    for (int q = 0; q < 2; q++) {
        int t = q ? t1 : t0;
        unsigned long long* oacc = q ? ob2 : oa;
        float inv_l = 1.0f / (q ? lb : la);
        int h = t >> 2, wsp = t & 3;
        float* op = out + ((size_t)(b * 256 + head * 32)) * 4096 + h * 64 + wsp * 16 + ww;
#pragma unroll
        for (int i = 0; i < 16; i++) {
            int d0 = 2 * i, d1 = 2 * i + 1;
            float lep0 = Bs[d0], lep1 = Bs[d1];
#pragma unroll
            for (int kh = 0; kh < 3; kh++) {
                int hn = h + kh - 1;
                if ((unsigned)hn < 64u) {
#pragma unroll
                    for (int kw = 0; kw < 3; kw++) {
                        int wn = wsp + kw - 1;
                        if ((unsigned)wn < 4u) {
                            int tn = hn * 4 + wn;
                            int kk2 = kh * 3 + kw;
                            lep0 = fmaf(Wt[kk2 * 32 + d0], Vs[tn * 36 + d0], lep0);
                            lep1 = fmaf(Wt[kk2 * 32 + d1], Vs[tn * 36 + d1], lep1);
                        }
                    }
                }
            }
            float ox, oy;
            unpack2(oacc[i], ox, oy);
            op[(size_t)d0 * 4096] = fmaf(ox, inv_l, lep0);
            op[(size_t)d1 * 4096] = fmaf(oy, inv_l, lep1);
        }
    }
}

extern "C" void kernel_launch(void* const* d_in, const int* in_sizes, int n_in,
                              void* d_out, int out_size) {
    const float* temp = (const float*)d_in[0];
    const float* gw = (const float*)d_in[1];
    const float* gb = (const float*)d_in[2];
    float* out = (float*)d_out;
    (void)in_sizes; (void)n_in; (void)out_size;

    cudaFuncSetAttribute(attn_kernel, cudaFuncAttributeMaxDynamicSharedMemorySize, 70912);

    repack_kernel<<<12288, 256>>>(temp);
    attn_kernel<<<1024, 128, 70912>>>(gw, gb, out);
}